// round 6
// baseline (speedup 1.0000x reference)
#include <cuda_runtime.h>
#include <cstdint>

// ---------------------------------------------------------------------------
// VectorQuantizer: z (32,256,32,32) f32 -> (z_q_st, loss, argmin indices)
//   z_flat = z.reshape(32768, 256); codebook (8192, 256)
//   d[n,k] = fl( fl(||z_n||^2 + ||e_k||^2) - fl(2 * dot(z_n, e_k)) )   (fp32!)
//   idx[n] = argmin_k d[n,k]  (first index on ties -- must match reference's
//            fp32-rounded tie structure, hence the explicit __f*_rn ops)
//   z_q_st = z + (z_q - z)  (evaluated in fp32, NOT simplified to z_q)
//   loss   = mean(diff^2) + 0.25*mean(diff^2)
// ---------------------------------------------------------------------------

#define N_ROWS       32768
#define DIM          256
#define KCODES       8192
#define TOTAL_ELEMS  (N_ROWS * DIM)   // 8388608

#define BM 128
#define BN 128
#define BK 32
#define TM 8
#define TN 8

// Scratch (no allocations allowed)
__device__ float g_znorm[N_ROWS];
__device__ float g_ce[KCODES];
__device__ int   g_indices[N_ROWS];
__device__ float g_loss;

// ---------------------------------------------------------------------------
// Row sum-of-squares, emulating an XLA-GPU style row reduction:
// one warp per row; lane L serially sums x[L + 32m]^2 (m=0..7), then a
// shfl_down tree (16,8,4,2,1). All adds via __fadd_rn (no FMA contraction).
// which==0 -> g_znorm (nrows=32768), which==1 -> g_ce (nrows=8192)
// ---------------------------------------------------------------------------
__global__ void rownorm_kernel(const float* __restrict__ x, int which, int nrows) {
    if (blockIdx.x == 0 && threadIdx.x == 0) g_loss = 0.0f;
    int warp = (blockIdx.x * blockDim.x + threadIdx.x) >> 5;
    int lane = threadIdx.x & 31;
    if (warp >= nrows) return;
    const float* row = x + (size_t)warp * DIM;
    float s = 0.0f;
#pragma unroll
    for (int m = 0; m < 8; ++m) {
        float v = row[lane + 32 * m];
        s = __fadd_rn(s, __fmul_rn(v, v));
    }
#pragma unroll
    for (int off = 16; off > 0; off >>= 1)
        s = __fadd_rn(s, __shfl_down_sync(0xffffffffu, s, off));
    if (lane == 0) {
        if (which == 0) g_znorm[warp] = s;
        else            g_ce[warp]    = s;
    }
}

// ---------------------------------------------------------------------------
// Fused GEMM + argmin.
// Block: 256 threads, computes a 128-row stripe vs ALL 8192 codes.
// Tiles: 128x128 output, K-chunks of 32 over DIM.
// Thread (ty,tx) = (tid>>4, tid&15) owns rows [ty*8,ty*8+8), cols [tx*8,tx*8+8).
// Global->SMEM: lane-per-row mapping (r = lane + 32i, d = 4*warpid) gives
// conflict-free transposed stores (bank = lane).
// ---------------------------------------------------------------------------
__global__ void __launch_bounds__(256, 2)
argmin_kernel(const float* __restrict__ z, const float* __restrict__ cb,
              float* __restrict__ out_idx_f) {
    __shared__ float As[BK * BM];
    __shared__ float Bs[BK * BN];
    __shared__ float ceS[BN];
    __shared__ float t1S[BM];

    const int tid = threadIdx.x;
    const int m0  = blockIdx.x * BM;
    const int tx  = tid & 15;
    const int ty  = tid >> 4;

    const int lane = tid & 31;        // row within 32-row group
    const int vc   = (tid >> 5) * 4;  // d-offset within BK (0,4,...,28)

    if (tid < BM) t1S[tid] = g_znorm[m0 + tid];

    float bestd[TM];
    int   besti[TM];
#pragma unroll
    for (int i = 0; i < TM; ++i) { bestd[i] = 3.4e38f; besti[i] = 0; }

    for (int nt = 0; nt < KCODES / BN; ++nt) {
        const int n0 = nt * BN;
        float acc[TM][TN];
#pragma unroll
        for (int i = 0; i < TM; ++i)
#pragma unroll
            for (int j = 0; j < TN; ++j) acc[i][j] = 0.0f;

        for (int kt = 0; kt < DIM / BK; ++kt) {
            const int d0 = kt * BK;
            __syncthreads();
#pragma unroll
            for (int i = 0; i < 4; ++i) {
                const int r = lane + 32 * i;
                float4 v = *(const float4*)(z + (size_t)(m0 + r) * DIM + d0 + vc);
                As[(vc + 0) * BM + r] = v.x;
                As[(vc + 1) * BM + r] = v.y;
                As[(vc + 2) * BM + r] = v.z;
                As[(vc + 3) * BM + r] = v.w;
            }
#pragma unroll
            for (int i = 0; i < 4; ++i) {
                const int r = lane + 32 * i;
                float4 v = *(const float4*)(cb + (size_t)(n0 + r) * DIM + d0 + vc);
                Bs[(vc + 0) * BN + r] = v.x;
                Bs[(vc + 1) * BN + r] = v.y;
                Bs[(vc + 2) * BN + r] = v.z;
                Bs[(vc + 3) * BN + r] = v.w;
            }
            if (kt == 0 && tid < BN) ceS[tid] = g_ce[n0 + tid];
            __syncthreads();

#pragma unroll
            for (int dd = 0; dd < BK; ++dd) {
                float af[TM], bf[TN];
                *(float4*)&af[0] = *(const float4*)&As[dd * BM + ty * TM];
                *(float4*)&af[4] = *(const float4*)&As[dd * BM + ty * TM + 4];
                *(float4*)&bf[0] = *(const float4*)&Bs[dd * BN + tx * TN];
                *(float4*)&bf[4] = *(const float4*)&Bs[dd * BN + tx * TN + 4];
#pragma unroll
                for (int i = 0; i < TM; ++i)
#pragma unroll
                    for (int j = 0; j < TN; ++j)
                        acc[i][j] = fmaf(af[i], bf[j], acc[i][j]);
            }
        }

        // Merge this 128-col tile into the running per-thread best.
        // d = fl( fl(t1 + ce) - fl(2*dot) ), exactly as the reference formula
        // rounds in fp32. Strict '<' keeps the FIRST (lowest) index on ties,
        // traversal is in ascending column order.
#pragma unroll
        for (int j = 0; j < TN; ++j) {
            const int   col = n0 + tx * TN + j;
            const float ce  = ceS[tx * TN + j];
#pragma unroll
            for (int i = 0; i < TM; ++i) {
                float T = __fadd_rn(t1S[ty * TM + i], ce);
                float d = __fsub_rn(T, __fmul_rn(2.0f, acc[i][j]));
                if (d < bestd[i]) { bestd[i] = d; besti[i] = col; }
            }
        }
    }

    // Cross-thread reduction: 16 candidates per row (one per tx).
    __syncthreads();
    float* sval = As;          // 128*16 floats, fits in As (4096 floats)
    int*   sidx = (int*)Bs;
#pragma unroll
    for (int i = 0; i < TM; ++i) {
        const int row = ty * TM + i;
        sval[row * 16 + tx] = bestd[i];
        sidx[row * 16 + tx] = besti[i];
    }
    __syncthreads();
    if (tid < BM) {
        float bv = sval[tid * 16];
        int   bi = sidx[tid * 16];
#pragma unroll
        for (int t = 1; t < 16; ++t) {
            float v  = sval[tid * 16 + t];
            int   id = sidx[tid * 16 + t];
            if (v < bv || (v == bv && id < bi)) { bv = v; bi = id; }
        }
        g_indices[m0 + tid] = bi;
        if (out_idx_f) out_idx_f[m0 + tid] = (float)bi;
    }
}

// ---------------------------------------------------------------------------
// Gather z_q, emit z_q_st = fl(z + fl(z_q - z)) (straight-through rounding!),
// and accumulate sum of diff^2 for the loss.
// ---------------------------------------------------------------------------
__global__ void gather_loss_kernel(const float* __restrict__ z,
                                   const float* __restrict__ cb,
                                   float* __restrict__ out_zq) {
    const int nvec = TOTAL_ELEMS / 4;
    float lsum = 0.0f;
    for (int i4 = blockIdx.x * blockDim.x + threadIdx.x; i4 < nvec;
         i4 += gridDim.x * blockDim.x) {
        const int row  = i4 >> 6;          // 64 float4 per 256-elem row
        const int dc   = (i4 & 63) << 2;
        const int code = g_indices[row];
        const float4 e  = *(const float4*)(cb + (size_t)code * DIM + dc);
        const float4 zz = *(const float4*)(z + (size_t)i4 * 4);
        float4 o;
        float d0 = __fsub_rn(e.x, zz.x); o.x = __fadd_rn(zz.x, d0);
        float d1 = __fsub_rn(e.y, zz.y); o.y = __fadd_rn(zz.y, d1);
        float d2 = __fsub_rn(e.z, zz.z); o.z = __fadd_rn(zz.z, d2);
        float d3 = __fsub_rn(e.w, zz.w); o.w = __fadd_rn(zz.w, d3);
        lsum += d0 * d0 + d1 * d1 + d2 * d2 + d3 * d3;
        *(float4*)(out_zq + (size_t)i4 * 4) = o;
    }
#pragma unroll
    for (int off = 16; off > 0; off >>= 1)
        lsum += __shfl_down_sync(0xffffffffu, lsum, off);
    __shared__ float wsum[8];
    if ((threadIdx.x & 31) == 0) wsum[threadIdx.x >> 5] = lsum;
    __syncthreads();
    if (threadIdx.x < 8) {
        float v = wsum[threadIdx.x];
#pragma unroll
        for (int off = 4; off > 0; off >>= 1)
            v += __shfl_down_sync(0x000000ffu, v, off);
        if (threadIdx.x == 0) atomicAdd(&g_loss, v);
    }
}

__global__ void finalize_kernel(float* __restrict__ out_loss) {
    float m = __fdiv_rn(g_loss, (float)TOTAL_ELEMS);
    out_loss[0] = __fadd_rn(m, __fmul_rn(0.25f, m));
}

// ---------------------------------------------------------------------------
// Launch: out layout assumed [z_q_st (8388608)] [loss (1)] [indices (32768)]
// in tuple order; adapts defensively via out_size.
// ---------------------------------------------------------------------------
extern "C" void kernel_launch(void* const* d_in, const int* in_sizes, int n_in,
                              void* d_out, int out_size) {
    const float* z  = (const float*)d_in[0];
    const float* cb = (const float*)d_in[1];
    float* out = (float*)d_out;

    float* out_zq   = out;
    float* out_loss = (out_size >= TOTAL_ELEMS + 1) ? (out + TOTAL_ELEMS) : nullptr;
    float* out_idx  = (out_size >= TOTAL_ELEMS + 1 + N_ROWS)
                        ? (out + TOTAL_ELEMS + 1) : nullptr;

    // 1) row norms (z and codebook) + zero loss accumulator
    rownorm_kernel<<<N_ROWS / 8, 256>>>(z, 0, N_ROWS);
    rownorm_kernel<<<KCODES / 8, 256>>>(cb, 1, KCODES);

    // 2) fused GEMM + argmin over 8192 codes
    argmin_kernel<<<N_ROWS / BM, 256>>>(z, cb, out_idx);

    // 3) gather z_q + straight-through output + loss partials
    gather_loss_kernel<<<2048, 256>>>(z, cb, out_zq);

    // 4) finalize loss
    if (out_loss) finalize_kernel<<<1, 1>>>(out_loss);
}

// round 12
// speedup vs baseline: 1.7058x; 1.7058x over previous
#include <cuda_runtime.h>
#include <cstdint>

// ---------------------------------------------------------------------------
// VectorQuantizer — tf32 mma.sync GEMM as candidate FILTER + exact fp32 fixup.
//   Stage 1: d_tf32[n,k] via single-pass tf32 tensor-core GEMM; collect all k
//            with d_tf32 <= runmin(slot)+EPS  (provable superset of exact-min
//            ties: |d_tf32 - d_fp32| <= 4e-5 hard bound, EPS = 2e-4).
//   Stage 2: fixup recomputes EXACT fp32 d (R6 rounding: ascending fmaf dot,
//            fl(fl(t1+ce)-fl(2*dot))) over survivors, lex (d, idx) argmin.
//   -> index decisions identical to the R6 kernel that passed at 2.9e-7.
// ---------------------------------------------------------------------------

#define N_ROWS       32768
#define DIM          256
#define KCODES       8192
#define TOTAL_ELEMS  (N_ROWS * DIM)

#define BM 128
#define BN 128
#define BK 32
#define NTILES (KCODES / BN)   // 64
#define KTILES (DIM / BK)      // 8
#define STRIDE 36              // SMEM row stride in floats (32 + 4 pad)

#define EPS   2.0e-4f          // >= 5x hard tf32-d error bound (4e-5)
#define CAP   256              // per-row candidate buffer
#define SCAP  64               // per-row survivor cap in fixup

// SMEM layout for GEMM (bytes, dynamic)
#define OFF_A 0
#define OFF_B (OFF_A + BM * STRIDE * 4)     // 18432
#define OFF_CE (OFF_B + BN * STRIDE * 4)    // 36864
#define SMEM_BYTES (OFF_CE + BN * 4)        // 37376

// Scratch (static device arrays; no allocations)
__device__ float g_znorm[N_ROWS];
__device__ float g_ce[KCODES];
__device__ int   g_indices[N_ROWS];
__device__ float g_loss;
__device__ int   g_ccount[N_ROWS];
__device__ int   g_cand_idx[N_ROWS * CAP];
__device__ float g_cand_d[N_ROWS * CAP];

__device__ __forceinline__ float tf32_rna(float x) {
    float r; asm("cvt.rna.tf32.f32 %0, %1;" : "=f"(r) : "f"(x)); return r;
}

// classic tensor-core MMA: m16n8k8, tf32 inputs (b32 regs), fp32 accum
__device__ __forceinline__ void mma_tf32(float* c, const uint32_t* a, const uint32_t* b) {
    asm volatile(
        "mma.sync.aligned.m16n8k8.row.col.f32.tf32.tf32.f32 "
        "{%0,%1,%2,%3}, {%4,%5,%6,%7}, {%8,%9}, {%0,%1,%2,%3};"
        : "+f"(c[0]), "+f"(c[1]), "+f"(c[2]), "+f"(c[3])
        : "r"(a[0]), "r"(a[1]), "r"(a[2]), "r"(a[3]), "r"(b[0]), "r"(b[1]));
}

// ---------------------------------------------------------------------------
// Row sum-of-squares (identical rounding to the R6 passing version).
// which==0 pass also zeroes g_ccount and g_loss.
// ---------------------------------------------------------------------------
__global__ void rownorm_kernel(const float* __restrict__ x, int which, int nrows) {
    int gi = blockIdx.x * blockDim.x + threadIdx.x;
    if (which == 0) {
        if (gi == 0) g_loss = 0.0f;
        if (gi < N_ROWS) g_ccount[gi] = 0;
    }
    int warp = gi >> 5;
    int lane = threadIdx.x & 31;
    if (warp >= nrows) return;
    const float* row = x + (size_t)warp * DIM;
    float s = 0.0f;
#pragma unroll
    for (int m = 0; m < 8; ++m) {
        float v = row[lane + 32 * m];
        s = __fadd_rn(s, __fmul_rn(v, v));
    }
#pragma unroll
    for (int off = 16; off > 0; off >>= 1)
        s = __fadd_rn(s, __shfl_down_sync(0xffffffffu, s, off));
    if (lane == 0) { if (which == 0) g_znorm[warp] = s; else g_ce[warp] = s; }
}

// ---------------------------------------------------------------------------
// Stage 1: single-pass tf32 GEMM + candidate collection.
// 256 threads = 8 warps: warp_m = wid&3 (32 rows), warp_n = wid>>2 (64 cols).
// tf32 conversion happens in the loader (global fp32 -> cvt.rna -> SMEM).
// ---------------------------------------------------------------------------
__global__ void __launch_bounds__(256, 2)
argmin_mma_kernel(const float* __restrict__ z, const float* __restrict__ cb) {
    extern __shared__ char smem[];
    uint32_t* As = (uint32_t*)(smem + OFF_A);
    uint32_t* Bs = (uint32_t*)(smem + OFF_B);
    float*    ceS = (float*)(smem + OFF_CE);

    const int tid    = threadIdx.x;
    const int lane   = tid & 31;
    const int wid    = tid >> 5;
    const int warp_m = wid & 3;
    const int warp_n = wid >> 2;
    const int m0     = blockIdx.x * BM;

    const int ar = tid & 127;              // loader row
    const int kg = (tid >> 7) * 16;        // loader k-base

    const int a_base = (warp_m * 32 + (lane >> 2)) * STRIDE + (lane & 3);
    const int b_base = (warp_n * 64 + (lane >> 2)) * STRIDE + (lane & 3);

    float t1v[4];
    float bestd[4];
    int   rows[4];
#pragma unroll
    for (int s = 0; s < 4; ++s) {
        const int rl = warp_m * 32 + (s >> 1) * 16 + (lane >> 2) + (s & 1) * 8;
        rows[s]  = m0 + rl;
        t1v[s]   = g_znorm[m0 + rl];
        bestd[s] = 3.4e38f;
    }

    for (int nt = 0; nt < NTILES; ++nt) {
        const int n0 = nt * BN;
        float acc[2][8][4];
#pragma unroll
        for (int i = 0; i < 2; ++i)
#pragma unroll
            for (int j = 0; j < 8; ++j)
#pragma unroll
                for (int c = 0; c < 4; ++c) acc[i][j][c] = 0.0f;

        for (int kt = 0; kt < KTILES; ++kt) {
            const int d0 = kt * BK;
            __syncthreads();
            if (kt == 0 && tid < BN) ceS[tid] = g_ce[n0 + tid];
            const size_t ga = (size_t)(m0 + ar) * DIM + d0 + kg;
            const size_t gb = (size_t)(n0 + ar) * DIM + d0 + kg;
#pragma unroll
            for (int q = 0; q < 4; ++q) {
                const int kk = kg + q * 4;
                float4 va = *(const float4*)(z + ga + q * 4);
                float4 ha;
                ha.x = tf32_rna(va.x); ha.y = tf32_rna(va.y);
                ha.z = tf32_rna(va.z); ha.w = tf32_rna(va.w);
                *(float4*)&As[ar * STRIDE + kk] = ha;
                float4 vb = *(const float4*)(cb + gb + q * 4);
                float4 hb;
                hb.x = tf32_rna(vb.x); hb.y = tf32_rna(vb.y);
                hb.z = tf32_rna(vb.z); hb.w = tf32_rna(vb.w);
                *(float4*)&Bs[ar * STRIDE + kk] = hb;
            }
            __syncthreads();

#pragma unroll
            for (int step = 0; step < 4; ++step) {
                const int k0 = step * 8;
                uint32_t af[2][4], bf[8][2];
#pragma unroll
                for (int i = 0; i < 2; ++i) {
                    const int o = a_base + i * 16 * STRIDE + k0;
                    af[i][0] = As[o];         af[i][1] = As[o + 8 * STRIDE];
                    af[i][2] = As[o + 4];     af[i][3] = As[o + 8 * STRIDE + 4];
                }
#pragma unroll
                for (int j = 0; j < 8; ++j) {
                    const int o = b_base + j * 8 * STRIDE + k0;
                    bf[j][0] = Bs[o]; bf[j][1] = Bs[o + 4];
                }
#pragma unroll
                for (int i = 0; i < 2; ++i)
#pragma unroll
                    for (int j = 0; j < 8; ++j) mma_tf32(acc[i][j], af[i], bf[j]);
            }
        }

        // epilogue: dT = fl(fl(t1+ce) - fl(2*dot_tf32)); collect candidates
        // within EPS of the per-slot running min (superset of exact ties).
#pragma unroll
        for (int j = 0; j < 8; ++j) {
            const int cl  = warp_n * 64 + j * 8 + 2 * (lane & 3);
            const float ce0 = ceS[cl];
            const float ce1 = ceS[cl + 1];
            const int g0 = n0 + cl;
#pragma unroll
            for (int i = 0; i < 2; ++i)
#pragma unroll
                for (int h = 0; h < 2; ++h) {
                    const int s = i * 2 + h;
                    const float dv0 = __fsub_rn(__fadd_rn(t1v[s], ce0),
                                                __fmul_rn(2.0f, acc[i][j][h * 2 + 0]));
                    if (dv0 <= bestd[s] + EPS) {
                        int p = atomicAdd(&g_ccount[rows[s]], 1);
                        if (p < CAP) {
                            g_cand_idx[rows[s] * CAP + p] = g0;
                            g_cand_d[rows[s] * CAP + p] = dv0;
                        }
                        if (dv0 < bestd[s]) bestd[s] = dv0;
                    }
                    const float dv1 = __fsub_rn(__fadd_rn(t1v[s], ce1),
                                                __fmul_rn(2.0f, acc[i][j][h * 2 + 1]));
                    if (dv1 <= bestd[s] + EPS) {
                        int p = atomicAdd(&g_ccount[rows[s]], 1);
                        if (p < CAP) {
                            g_cand_idx[rows[s] * CAP + p] = g0 + 1;
                            g_cand_d[rows[s] * CAP + p] = dv1;
                        }
                        if (dv1 < bestd[s]) bestd[s] = dv1;
                    }
                }
        }
    }
}

// ---------------------------------------------------------------------------
// Stage 2: exact fp32 fixup. One warp per row.
// Recomputes d with R6's exact rounding over survivors; lex (d, idx) argmin.
// Deterministic: decision is a pure function of the candidate SET.
// ---------------------------------------------------------------------------
__global__ void __launch_bounds__(256)
fixup_kernel(const float* __restrict__ z, const float* __restrict__ cb,
             float* __restrict__ out_idx_f) {
    __shared__ float zrow_s[8][DIM];
    __shared__ int   surv_s[8][SCAP];
    __shared__ int   scount[8];

    const int gw   = (blockIdx.x * blockDim.x + threadIdx.x) >> 5;
    const int lane = threadIdx.x & 31;
    const int w    = threadIdx.x >> 5;
    if (gw >= N_ROWS) return;
    const int row = gw;

    const float* zr = z + (size_t)row * DIM;
    for (int i = lane; i < DIM; i += 32) zrow_s[w][i] = zr[i];
    if (lane == 0) scount[w] = 0;
    __syncwarp();

    const int cnt = g_ccount[row];
    bool fallback = (cnt > CAP);

    if (!fallback) {
        float mn = 3.4e38f;
        for (int e = lane; e < cnt; e += 32)
            mn = fminf(mn, g_cand_d[row * CAP + e]);
#pragma unroll
        for (int off = 16; off > 0; off >>= 1)
            mn = fminf(mn, __shfl_xor_sync(0xffffffffu, mn, off));
        for (int e = lane; e < cnt; e += 32) {
            if (g_cand_d[row * CAP + e] <= mn + EPS) {
                int p = atomicAdd(&scount[w], 1);
                if (p < SCAP) surv_s[w][p] = g_cand_idx[row * CAP + e];
            }
        }
        __syncwarp();
        if (scount[w] > SCAP) fallback = true;
    }

    const float t1 = g_znorm[row];
    float bd = 3.4e38f;
    int   bi = 0x7fffffff;

    if (!fallback) {
        const int ns = scount[w];
        for (int s = lane; s < ns; s += 32) {
            const int k = surv_s[w][s];
            const float* e = cb + (size_t)k * DIM;
            float acc = 0.0f;
#pragma unroll 8
            for (int d = 0; d < DIM; ++d) acc = fmaf(zrow_s[w][d], e[d], acc);
            const float dv = __fsub_rn(__fadd_rn(t1, g_ce[k]),
                                       __fmul_rn(2.0f, acc));
            if (dv < bd || (dv == bd && k < bi)) { bd = dv; bi = k; }
        }
    } else {
        for (int k = lane; k < KCODES; k += 32) {
            const float* e = cb + (size_t)k * DIM;
            float acc = 0.0f;
#pragma unroll 8
            for (int d = 0; d < DIM; ++d) acc = fmaf(zrow_s[w][d], e[d], acc);
            const float dv = __fsub_rn(__fadd_rn(t1, g_ce[k]),
                                       __fmul_rn(2.0f, acc));
            if (dv < bd || (dv == bd && k < bi)) { bd = dv; bi = k; }
        }
    }
#pragma unroll
    for (int off = 16; off > 0; off >>= 1) {
        const float od = __shfl_down_sync(0xffffffffu, bd, off);
        const int   oi = __shfl_down_sync(0xffffffffu, bi, off);
        if (od < bd || (od == bd && oi < bi)) { bd = od; bi = oi; }
    }
    if (lane == 0) {
        g_indices[row] = bi;
        if (out_idx_f) out_idx_f[row] = (float)bi;
    }
}

// ---------------------------------------------------------------------------
// Gather z_q, z_q_st = fl(z + fl(z_q - z)), loss partial sums (unchanged)
// ---------------------------------------------------------------------------
__global__ void gather_loss_kernel(const float* __restrict__ z,
                                   const float* __restrict__ cb,
                                   float* __restrict__ out_zq) {
    const int nvec = TOTAL_ELEMS / 4;
    float lsum = 0.0f;
    for (int i4 = blockIdx.x * blockDim.x + threadIdx.x; i4 < nvec;
         i4 += gridDim.x * blockDim.x) {
        const int row  = i4 >> 6;
        const int dc   = (i4 & 63) << 2;
        const int code = g_indices[row];
        const float4 e  = *(const float4*)(cb + (size_t)code * DIM + dc);
        const float4 zz = *(const float4*)(z + (size_t)i4 * 4);
        float4 o;
        float d0 = __fsub_rn(e.x, zz.x); o.x = __fadd_rn(zz.x, d0);
        float d1 = __fsub_rn(e.y, zz.y); o.y = __fadd_rn(zz.y, d1);
        float d2 = __fsub_rn(e.z, zz.z); o.z = __fadd_rn(zz.z, d2);
        float d3 = __fsub_rn(e.w, zz.w); o.w = __fadd_rn(zz.w, d3);
        lsum += d0 * d0 + d1 * d1 + d2 * d2 + d3 * d3;
        *(float4*)(out_zq + (size_t)i4 * 4) = o;
    }
#pragma unroll
    for (int off = 16; off > 0; off >>= 1)
        lsum += __shfl_down_sync(0xffffffffu, lsum, off);
    __shared__ float wsum[8];
    if ((threadIdx.x & 31) == 0) wsum[threadIdx.x >> 5] = lsum;
    __syncthreads();
    if (threadIdx.x < 8) {
        float v = wsum[threadIdx.x];
#pragma unroll
        for (int off = 4; off > 0; off >>= 1)
            v += __shfl_down_sync(0x000000ffu, v, off);
        if (threadIdx.x == 0) atomicAdd(&g_loss, v);
    }
}

__global__ void finalize_kernel(float* __restrict__ out_loss) {
    float m = __fdiv_rn(g_loss, (float)TOTAL_ELEMS);
    out_loss[0] = __fadd_rn(m, __fmul_rn(0.25f, m));
}

// ---------------------------------------------------------------------------
extern "C" void kernel_launch(void* const* d_in, const int* in_sizes, int n_in,
                              void* d_out, int out_size) {
    const float* z  = (const float*)d_in[0];
    const float* cb = (const float*)d_in[1];
    float* out = (float*)d_out;

    float* out_zq   = out;
    float* out_loss = (out_size >= TOTAL_ELEMS + 1) ? (out + TOTAL_ELEMS) : nullptr;
    float* out_idx  = (out_size >= TOTAL_ELEMS + 1 + N_ROWS)
                        ? (out + TOTAL_ELEMS + 1) : nullptr;

    cudaFuncSetAttribute(argmin_mma_kernel,
                         cudaFuncAttributeMaxDynamicSharedMemorySize, SMEM_BYTES);

    // 1) row norms + zero loss + zero candidate counters
    rownorm_kernel<<<N_ROWS / 8, 256>>>(z, 0, N_ROWS);
    rownorm_kernel<<<KCODES / 8, 256>>>(cb, 1, KCODES);

    // 2) tf32 tensor-core GEMM -> candidate shortlist
    argmin_mma_kernel<<<N_ROWS / BM, 256, SMEM_BYTES>>>(z, cb);

    // 3) exact fp32 fixup -> final indices
    fixup_kernel<<<(N_ROWS * 32) / 256, 256>>>(z, cb, out_idx);

    // 4) outputs
    gather_loss_kernel<<<2048, 256>>>(z, cb, out_zq);
    if (out_loss) finalize_kernel<<<1, 1>>>(out_loss);
}

// round 14
// speedup vs baseline: 1.8702x; 1.0964x over previous
#include <cuda_runtime.h>
#include <cstdint>

// ---------------------------------------------------------------------------
// VectorQuantizer — tf32 mma.sync GEMM filter (cp.async double-buffered)
//                   + exact fp32 fixup (validated in R12).
//   Stage 0: pre-convert z, cb to tf32(rna) scratch once.
//   Stage 1: d_tf32 via tensor-core GEMM, collect k with dT <= runmin+EPS.
//   Stage 2: exact fp32 recompute (R6 rounding) over survivors -> indices.
// ---------------------------------------------------------------------------

#define N_ROWS       32768
#define DIM          256
#define KCODES       8192
#define TOTAL_ELEMS  (N_ROWS * DIM)
#define CB_ELEMS     (KCODES * DIM)

#define BM 128
#define BN 128
#define BK 32
#define NTILES (KCODES / BN)     // 64
#define KTILES (DIM / BK)        // 8
#define NCHUNKS (NTILES * KTILES) // 512
#define STRIDE 36                // SMEM row stride in floats (32 + 4 pad)

#define EPS   2.0e-4f            // >= 5x hard tf32(rna)-d error bound (4e-5)
#define CAP   256
#define SCAP  64

// SMEM: two stages of (A tile + B tile), then ce
#define TILE_BYTES   (BM * STRIDE * 4)         // 18432
#define STAGE_BYTES  (2 * TILE_BYTES)          // 36864 (A then B)
#define OFF_CE       (2 * STAGE_BYTES)         // 73728
#define SMEM_BYTES   (OFF_CE + BN * 4)         // 74240

// Scratch (static device arrays; no allocations)
__device__ float g_znorm[N_ROWS];
__device__ float g_ce[KCODES];
__device__ int   g_indices[N_ROWS];
__device__ float g_loss;
__device__ int   g_ccount[N_ROWS];
__device__ int   g_cand_idx[N_ROWS * CAP];
__device__ float g_cand_d[N_ROWS * CAP];
__device__ float g_ztf[TOTAL_ELEMS];
__device__ float g_ctf[CB_ELEMS];

__device__ __forceinline__ float tf32_rna(float x) {
    float r; asm("cvt.rna.tf32.f32 %0, %1;" : "=f"(r) : "f"(x)); return r;
}

__device__ __forceinline__ void mma_tf32(float* c, const uint32_t* a, const uint32_t* b) {
    asm volatile(
        "mma.sync.aligned.m16n8k8.row.col.f32.tf32.tf32.f32 "
        "{%0,%1,%2,%3}, {%4,%5,%6,%7}, {%8,%9}, {%0,%1,%2,%3};"
        : "+f"(c[0]), "+f"(c[1]), "+f"(c[2]), "+f"(c[3])
        : "r"(a[0]), "r"(a[1]), "r"(a[2]), "r"(a[3]), "r"(b[0]), "r"(b[1]));
}

__device__ __forceinline__ void cp_async16(uint32_t saddr, const float* g) {
    asm volatile("cp.async.cg.shared.global [%0], [%1], 16;" :: "r"(saddr), "l"(g));
}
#define CP_COMMIT()  asm volatile("cp.async.commit_group;" ::: "memory")
#define CP_WAIT1()   asm volatile("cp.async.wait_group 1;" ::: "memory")

// ---------------------------------------------------------------------------
// Row sum-of-squares (identical rounding to R6/R12 passing versions).
// which==0 pass also zeroes g_ccount and g_loss.
// ---------------------------------------------------------------------------
__global__ void rownorm_kernel(const float* __restrict__ x, int which, int nrows) {
    int gi = blockIdx.x * blockDim.x + threadIdx.x;
    if (which == 0) {
        if (gi == 0) g_loss = 0.0f;
        if (gi < N_ROWS) g_ccount[gi] = 0;
    }
    int warp = gi >> 5;
    int lane = threadIdx.x & 31;
    if (warp >= nrows) return;
    const float* row = x + (size_t)warp * DIM;
    float s = 0.0f;
#pragma unroll
    for (int m = 0; m < 8; ++m) {
        float v = row[lane + 32 * m];
        s = __fadd_rn(s, __fmul_rn(v, v));
    }
#pragma unroll
    for (int off = 16; off > 0; off >>= 1)
        s = __fadd_rn(s, __shfl_down_sync(0xffffffffu, s, off));
    if (lane == 0) { if (which == 0) g_znorm[warp] = s; else g_ce[warp] = s; }
}

// ---------------------------------------------------------------------------
// Stage 0: tf32(rna) pre-convert (memory-bound one-pass)
// ---------------------------------------------------------------------------
__global__ void cvt_kernel(const float* __restrict__ x, float* __restrict__ y, int n4) {
    int i = blockIdx.x * blockDim.x + threadIdx.x;
    if (i >= n4) return;
    float4 v = ((const float4*)x)[i];
    float4 h;
    h.x = tf32_rna(v.x); h.y = tf32_rna(v.y);
    h.z = tf32_rna(v.z); h.w = tf32_rna(v.w);
    ((float4*)y)[i] = h;
}

// ---------------------------------------------------------------------------
// Stage 1: cp.async double-buffered tf32 GEMM + candidate collection.
// 256 threads = 8 warps: warp_m = wid&3 (32 rows), warp_n = wid>>2 (64 cols).
// ---------------------------------------------------------------------------
__global__ void __launch_bounds__(256, 2)
argmin_mma_kernel(const float* __restrict__ ztf, const float* __restrict__ ctf) {
    extern __shared__ char smem[];
    float* ceS = (float*)(smem + OFF_CE);
    const uint32_t smem_s = (uint32_t)__cvta_generic_to_shared(smem);

    const int tid    = threadIdx.x;
    const int lane   = tid & 31;
    const int wid    = tid >> 5;
    const int warp_m = wid & 3;
    const int warp_n = wid >> 2;
    const int m0     = blockIdx.x * BM;

    // loader mapping: 2 threads per row, 64B contiguous each
    const int lrow  = tid & 127;
    const int lhalf = tid >> 7;            // 0/1 -> float offset 0/16

    const int a_base = (warp_m * 32 + (lane >> 2)) * STRIDE + (lane & 3);
    const int b_base = (warp_n * 64 + (lane >> 2)) * STRIDE + (lane & 3);

    float t1v[4];
    float bestd[4];
    int   rows[4];
#pragma unroll
    for (int s = 0; s < 4; ++s) {
        const int rl = warp_m * 32 + (s >> 1) * 16 + (lane >> 2) + (s & 1) * 8;
        rows[s]  = m0 + rl;
        t1v[s]   = g_znorm[m0 + rl];
        bestd[s] = 3.4e38f;
    }

    // chunk loader: chunk c -> stage buf
    auto load_chunk = [&](int c, int buf) {
        const int nt = c >> 3, kt = c & 7;
        const size_t ga = (size_t)(m0 + lrow) * DIM + kt * BK + lhalf * 16;
        const size_t gb = (size_t)(nt * BN + lrow) * DIM + kt * BK + lhalf * 16;
        const uint32_t sa = smem_s + buf * STAGE_BYTES
                          + (uint32_t)(lrow * STRIDE + lhalf * 16) * 4;
        const uint32_t sb = sa + TILE_BYTES;
#pragma unroll
        for (int q = 0; q < 4; ++q) {
            cp_async16(sa + q * 16, ztf + ga + q * 4);
            cp_async16(sb + q * 16, ctf + gb + q * 4);
        }
    };

    float acc[2][8][4];

    // prologue: prefetch chunk 0
    load_chunk(0, 0);
    CP_COMMIT();

    for (int c = 0; c < NCHUNKS; ++c) {
        const int nt = c >> 3, kt = c & 7;
        const int buf = c & 1;
        if (c + 1 < NCHUNKS) load_chunk(c + 1, (c + 1) & 1);
        CP_COMMIT();
        CP_WAIT1();                 // stage `buf` ready
        __syncthreads();

        if (kt == 0) {
            if (tid < BN) ceS[tid] = g_ce[nt * BN + tid];
#pragma unroll
            for (int i = 0; i < 2; ++i)
#pragma unroll
                for (int j = 0; j < 8; ++j)
#pragma unroll
                    for (int q = 0; q < 4; ++q) acc[i][j][q] = 0.0f;
        }

        const uint32_t* As = (const uint32_t*)(smem + buf * STAGE_BYTES);
        const uint32_t* Bs = (const uint32_t*)(smem + buf * STAGE_BYTES + TILE_BYTES);

#pragma unroll
        for (int step = 0; step < 4; ++step) {
            const int k0 = step * 8;
            uint32_t af[2][4], bf[8][2];
#pragma unroll
            for (int i = 0; i < 2; ++i) {
                const int o = a_base + i * 16 * STRIDE + k0;
                af[i][0] = As[o];         af[i][1] = As[o + 8 * STRIDE];
                af[i][2] = As[o + 4];     af[i][3] = As[o + 8 * STRIDE + 4];
            }
#pragma unroll
            for (int j = 0; j < 8; ++j) {
                const int o = b_base + j * 8 * STRIDE + k0;
                bf[j][0] = Bs[o]; bf[j][1] = Bs[o + 4];
            }
#pragma unroll
            for (int i = 0; i < 2; ++i)
#pragma unroll
                for (int j = 0; j < 8; ++j) mma_tf32(acc[i][j], af[i], bf[j]);
        }

        if (kt == 7) {
            // epilogue for tile nt: dT = fl(fl(t1+ce) - fl(2*dot)); collect
            const int n0 = nt * BN;
#pragma unroll
            for (int j = 0; j < 8; ++j) {
                const int cl  = warp_n * 64 + j * 8 + 2 * (lane & 3);
                const float ce0 = ceS[cl];
                const float ce1 = ceS[cl + 1];
                const int g0 = n0 + cl;
#pragma unroll
                for (int i = 0; i < 2; ++i)
#pragma unroll
                    for (int h = 0; h < 2; ++h) {
                        const int s = i * 2 + h;
                        const float dv0 = __fsub_rn(__fadd_rn(t1v[s], ce0),
                                                    __fmul_rn(2.0f, acc[i][j][h * 2 + 0]));
                        if (dv0 <= bestd[s] + EPS) {
                            int p = atomicAdd(&g_ccount[rows[s]], 1);
                            if (p < CAP) {
                                g_cand_idx[rows[s] * CAP + p] = g0;
                                g_cand_d[rows[s] * CAP + p] = dv0;
                            }
                            if (dv0 < bestd[s]) bestd[s] = dv0;
                        }
                        const float dv1 = __fsub_rn(__fadd_rn(t1v[s], ce1),
                                                    __fmul_rn(2.0f, acc[i][j][h * 2 + 1]));
                        if (dv1 <= bestd[s] + EPS) {
                            int p = atomicAdd(&g_ccount[rows[s]], 1);
                            if (p < CAP) {
                                g_cand_idx[rows[s] * CAP + p] = g0 + 1;
                                g_cand_d[rows[s] * CAP + p] = dv1;
                            }
                            if (dv1 < bestd[s]) bestd[s] = dv1;
                        }
                    }
            }
        }
        __syncthreads();   // protect stage `buf` before iter c+1 prefetches into it
    }
}

// ---------------------------------------------------------------------------
// Stage 2: exact fp32 fixup (unchanged from R12 — validated).
// ---------------------------------------------------------------------------
__global__ void __launch_bounds__(256)
fixup_kernel(const float* __restrict__ z, const float* __restrict__ cb,
             float* __restrict__ out_idx_f) {
    __shared__ float zrow_s[8][DIM];
    __shared__ int   surv_s[8][SCAP];
    __shared__ int   scount[8];

    const int gw   = (blockIdx.x * blockDim.x + threadIdx.x) >> 5;
    const int lane = threadIdx.x & 31;
    const int w    = threadIdx.x >> 5;
    if (gw >= N_ROWS) return;
    const int row = gw;

    const float* zr = z + (size_t)row * DIM;
    for (int i = lane; i < DIM; i += 32) zrow_s[w][i] = zr[i];
    if (lane == 0) scount[w] = 0;
    __syncwarp();

    const int cnt = g_ccount[row];
    bool fallback = (cnt > CAP);

    if (!fallback) {
        float mn = 3.4e38f;
        for (int e = lane; e < cnt; e += 32)
            mn = fminf(mn, g_cand_d[row * CAP + e]);
#pragma unroll
        for (int off = 16; off > 0; off >>= 1)
            mn = fminf(mn, __shfl_xor_sync(0xffffffffu, mn, off));
        for (int e = lane; e < cnt; e += 32) {
            if (g_cand_d[row * CAP + e] <= mn + EPS) {
                int p = atomicAdd(&scount[w], 1);
                if (p < SCAP) surv_s[w][p] = g_cand_idx[row * CAP + e];
            }
        }
        __syncwarp();
        if (scount[w] > SCAP) fallback = true;
    }

    const float t1 = g_znorm[row];
    float bd = 3.4e38f;
    int   bi = 0x7fffffff;

    if (!fallback) {
        const int ns = scount[w];
        for (int s = lane; s < ns; s += 32) {
            const int k = surv_s[w][s];
            const float* e = cb + (size_t)k * DIM;
            float acc = 0.0f;
#pragma unroll 8
            for (int d = 0; d < DIM; ++d) acc = fmaf(zrow_s[w][d], e[d], acc);
            const float dv = __fsub_rn(__fadd_rn(t1, g_ce[k]),
                                       __fmul_rn(2.0f, acc));
            if (dv < bd || (dv == bd && k < bi)) { bd = dv; bi = k; }
        }
    } else {
        for (int k = lane; k < KCODES; k += 32) {
            const float* e = cb + (size_t)k * DIM;
            float acc = 0.0f;
#pragma unroll 8
            for (int d = 0; d < DIM; ++d) acc = fmaf(zrow_s[w][d], e[d], acc);
            const float dv = __fsub_rn(__fadd_rn(t1, g_ce[k]),
                                       __fmul_rn(2.0f, acc));
            if (dv < bd || (dv == bd && k < bi)) { bd = dv; bi = k; }
        }
    }
#pragma unroll
    for (int off = 16; off > 0; off >>= 1) {
        const float od = __shfl_down_sync(0xffffffffu, bd, off);
        const int   oi = __shfl_down_sync(0xffffffffu, bi, off);
        if (od < bd || (od == bd && oi < bi)) { bd = od; bi = oi; }
    }
    if (lane == 0) {
        g_indices[row] = bi;
        if (out_idx_f) out_idx_f[row] = (float)bi;
    }
}

// ---------------------------------------------------------------------------
// Gather + straight-through output + loss (unchanged — validated)
// ---------------------------------------------------------------------------
__global__ void gather_loss_kernel(const float* __restrict__ z,
                                   const float* __restrict__ cb,
                                   float* __restrict__ out_zq) {
    const int nvec = TOTAL_ELEMS / 4;
    float lsum = 0.0f;
    for (int i4 = blockIdx.x * blockDim.x + threadIdx.x; i4 < nvec;
         i4 += gridDim.x * blockDim.x) {
        const int row  = i4 >> 6;
        const int dc   = (i4 & 63) << 2;
        const int code = g_indices[row];
        const float4 e  = *(const float4*)(cb + (size_t)code * DIM + dc);
        const float4 zz = *(const float4*)(z + (size_t)i4 * 4);
        float4 o;
        float d0 = __fsub_rn(e.x, zz.x); o.x = __fadd_rn(zz.x, d0);
        float d1 = __fsub_rn(e.y, zz.y); o.y = __fadd_rn(zz.y, d1);
        float d2 = __fsub_rn(e.z, zz.z); o.z = __fadd_rn(zz.z, d2);
        float d3 = __fsub_rn(e.w, zz.w); o.w = __fadd_rn(zz.w, d3);
        lsum += d0 * d0 + d1 * d1 + d2 * d2 + d3 * d3;
        *(float4*)(out_zq + (size_t)i4 * 4) = o;
    }
#pragma unroll
    for (int off = 16; off > 0; off >>= 1)
        lsum += __shfl_down_sync(0xffffffffu, lsum, off);
    __shared__ float wsum[8];
    if ((threadIdx.x & 31) == 0) wsum[threadIdx.x >> 5] = lsum;
    __syncthreads();
    if (threadIdx.x < 8) {
        float v = wsum[threadIdx.x];
#pragma unroll
        for (int off = 4; off > 0; off >>= 1)
            v += __shfl_down_sync(0x000000ffu, v, off);
        if (threadIdx.x == 0) atomicAdd(&g_loss, v);
    }
}

__global__ void finalize_kernel(float* __restrict__ out_loss) {
    float m = __fdiv_rn(g_loss, (float)TOTAL_ELEMS);
    out_loss[0] = __fadd_rn(m, __fmul_rn(0.25f, m));
}

// ---------------------------------------------------------------------------
extern "C" void kernel_launch(void* const* d_in, const int* in_sizes, int n_in,
                              void* d_out, int out_size) {
    const float* z  = (const float*)d_in[0];
    const float* cb = (const float*)d_in[1];
    float* out = (float*)d_out;

    float* out_zq   = out;
    float* out_loss = (out_size >= TOTAL_ELEMS + 1) ? (out + TOTAL_ELEMS) : nullptr;
    float* out_idx  = (out_size >= TOTAL_ELEMS + 1 + N_ROWS)
                        ? (out + TOTAL_ELEMS + 1) : nullptr;

    cudaFuncSetAttribute(argmin_mma_kernel,
                         cudaFuncAttributeMaxDynamicSharedMemorySize, SMEM_BYTES);

    float *ztf, *ctf;
    cudaGetSymbolAddress((void**)&ztf, g_ztf);
    cudaGetSymbolAddress((void**)&ctf, g_ctf);

    // 1) row norms + zero loss/counters; tf32 pre-convert
    rownorm_kernel<<<N_ROWS / 8, 256>>>(z, 0, N_ROWS);
    rownorm_kernel<<<KCODES / 8, 256>>>(cb, 1, KCODES);
    cvt_kernel<<<TOTAL_ELEMS / 4 / 256, 256>>>(z, ztf, TOTAL_ELEMS / 4);
    cvt_kernel<<<CB_ELEMS / 4 / 256, 256>>>(cb, ctf, CB_ELEMS / 4);

    // 2) pipelined tf32 tensor-core GEMM -> candidate shortlist
    argmin_mma_kernel<<<N_ROWS / BM, 256, SMEM_BYTES>>>(ztf, ctf);

    // 3) exact fp32 fixup -> final indices
    fixup_kernel<<<(N_ROWS * 32) / 256, 256>>>(z, cb, out_idx);

    // 4) outputs
    gather_loss_kernel<<<2048, 256>>>(z, cb, out_zq);
    if (out_loss) finalize_kernel<<<1, 1>>>(out_loss);
}

// round 15
// speedup vs baseline: 1.8847x; 1.0077x over previous
#include <cuda_runtime.h>
#include <cstdint>

// ---------------------------------------------------------------------------
// VectorQuantizer — tf32 mma.sync GEMM filter, 3-stage cp.async pipeline,
//                   + exact fp32 fixup (validated R12/R14).
//   Stage 0: pre-convert z, cb to tf32(rna) scratch once.
//   Stage 1: d_tf32 via tensor-core GEMM, collect k with dT <= runmin+EPS.
//   Stage 2: exact fp32 recompute (R6 rounding) over survivors -> indices.
// ---------------------------------------------------------------------------

#define N_ROWS       32768
#define DIM          256
#define KCODES       8192
#define TOTAL_ELEMS  (N_ROWS * DIM)
#define CB_ELEMS     (KCODES * DIM)

#define BM 128
#define BN 128
#define BK 32
#define NTILES (KCODES / BN)      // 64
#define KTILES (DIM / BK)         // 8
#define NCHUNKS (NTILES * KTILES) // 512
#define STRIDE 36                 // SMEM row stride in floats (32 + 4 pad)
#define STAGES 3

#define EPS   2.0e-4f             // >= 5x hard tf32(rna)-d error bound (4e-5)
#define CAP   256
#define SCAP  64

#define TILE_BYTES   (BM * STRIDE * 4)          // 18432
#define STAGE_BYTES  (2 * TILE_BYTES)           // 36864 (A then B)
#define OFF_CE       (STAGES * STAGE_BYTES)     // 110592 (2 x 512B, by tile parity)
#define SMEM_BYTES   (OFF_CE + 2 * BN * 4)      // 111616

// Scratch (static device arrays; no allocations)
__device__ float g_znorm[N_ROWS];
__device__ float g_ce[KCODES];
__device__ int   g_indices[N_ROWS];
__device__ float g_loss;
__device__ int   g_ccount[N_ROWS];
__device__ int   g_cand_idx[N_ROWS * CAP];
__device__ float g_cand_d[N_ROWS * CAP];
__device__ float g_ztf[TOTAL_ELEMS];
__device__ float g_ctf[CB_ELEMS];

__device__ __forceinline__ float tf32_rna(float x) {
    float r; asm("cvt.rna.tf32.f32 %0, %1;" : "=f"(r) : "f"(x)); return r;
}

__device__ __forceinline__ void mma_tf32(float* c, const uint32_t* a, const uint32_t* b) {
    asm volatile(
        "mma.sync.aligned.m16n8k8.row.col.f32.tf32.tf32.f32 "
        "{%0,%1,%2,%3}, {%4,%5,%6,%7}, {%8,%9}, {%0,%1,%2,%3};"
        : "+f"(c[0]), "+f"(c[1]), "+f"(c[2]), "+f"(c[3])
        : "r"(a[0]), "r"(a[1]), "r"(a[2]), "r"(a[3]), "r"(b[0]), "r"(b[1]));
}

__device__ __forceinline__ void cp_async16(uint32_t saddr, const float* g) {
    asm volatile("cp.async.cg.shared.global [%0], [%1], 16;" :: "r"(saddr), "l"(g));
}
#define CP_COMMIT()  asm volatile("cp.async.commit_group;" ::: "memory")
#define CP_WAIT1()   asm volatile("cp.async.wait_group 1;" ::: "memory")

// ---------------------------------------------------------------------------
// Row sum-of-squares (identical rounding to R6/R12 passing versions).
// which==0 pass also zeroes g_ccount and g_loss.
// ---------------------------------------------------------------------------
__global__ void rownorm_kernel(const float* __restrict__ x, int which, int nrows) {
    int gi = blockIdx.x * blockDim.x + threadIdx.x;
    if (which == 0) {
        if (gi == 0) g_loss = 0.0f;
        if (gi < N_ROWS) g_ccount[gi] = 0;
    }
    int warp = gi >> 5;
    int lane = threadIdx.x & 31;
    if (warp >= nrows) return;
    const float* row = x + (size_t)warp * DIM;
    float s = 0.0f;
#pragma unroll
    for (int m = 0; m < 8; ++m) {
        float v = row[lane + 32 * m];
        s = __fadd_rn(s, __fmul_rn(v, v));
    }
#pragma unroll
    for (int off = 16; off > 0; off >>= 1)
        s = __fadd_rn(s, __shfl_down_sync(0xffffffffu, s, off));
    if (lane == 0) { if (which == 0) g_znorm[warp] = s; else g_ce[warp] = s; }
}

// ---------------------------------------------------------------------------
// Stage 0: tf32(rna) pre-convert (memory-bound one-pass)
// ---------------------------------------------------------------------------
__global__ void cvt_kernel(const float* __restrict__ x, float* __restrict__ y, int n4) {
    int i = blockIdx.x * blockDim.x + threadIdx.x;
    if (i >= n4) return;
    float4 v = ((const float4*)x)[i];
    float4 h;
    h.x = tf32_rna(v.x); h.y = tf32_rna(v.y);
    h.z = tf32_rna(v.z); h.w = tf32_rna(v.w);
    ((float4*)y)[i] = h;
}

// ---------------------------------------------------------------------------
// Stage 1: 3-stage cp.async tf32 GEMM + candidate collection.
// One __syncthreads per chunk; loads for chunk c+2 issued after the barrier
// into stage (c+2)%3 == (c-1)%3 (freed by that same barrier). ce loads ride
// the cp.async stream, double-buffered by tile parity.
// ---------------------------------------------------------------------------
__global__ void __launch_bounds__(256, 2)
argmin_mma_kernel(const float* __restrict__ ztf, const float* __restrict__ ctf) {
    extern __shared__ char smem[];
    float* ceS = (float*)(smem + OFF_CE);
    const uint32_t smem_s = (uint32_t)__cvta_generic_to_shared(smem);

    const int tid    = threadIdx.x;
    const int lane   = tid & 31;
    const int wid    = tid >> 5;
    const int warp_m = wid & 3;
    const int warp_n = wid >> 2;
    const int m0     = blockIdx.x * BM;

    const int lrow  = tid & 127;
    const int lhalf = tid >> 7;            // 0/1 -> float offset 0/16

    const int a_base = (warp_m * 32 + (lane >> 2)) * STRIDE + (lane & 3);
    const int b_base = (warp_n * 64 + (lane >> 2)) * STRIDE + (lane & 3);

    float t1v[4];
    float bestd[4];
    int   rows[4];
#pragma unroll
    for (int s = 0; s < 4; ++s) {
        const int rl = warp_m * 32 + (s >> 1) * 16 + (lane >> 2) + (s & 1) * 8;
        rows[s]  = m0 + rl;
        t1v[s]   = g_znorm[m0 + rl];
        bestd[s] = 3.4e38f;
    }

    // chunk loader: chunk c -> stage buf; kt==0 also streams ce for its tile
    auto load_chunk = [&](int c, int buf) {
        const int nt = c >> 3, kt = c & 7;
        const size_t ga = (size_t)(m0 + lrow) * DIM + kt * BK + lhalf * 16;
        const size_t gb = (size_t)(nt * BN + lrow) * DIM + kt * BK + lhalf * 16;
        const uint32_t sa = smem_s + buf * STAGE_BYTES
                          + (uint32_t)(lrow * STRIDE + lhalf * 16) * 4;
        const uint32_t sb = sa + TILE_BYTES;
#pragma unroll
        for (int q = 0; q < 4; ++q) {
            cp_async16(sa + q * 16, ztf + ga + q * 4);
            cp_async16(sb + q * 16, ctf + gb + q * 4);
        }
        if (kt == 0 && tid < 32)
            cp_async16(smem_s + OFF_CE + (uint32_t)(nt & 1) * (BN * 4) + tid * 16,
                       g_ce + nt * BN + tid * 4);
    };

    float acc[2][8][4];

    // prologue: prefetch chunks 0 and 1 (separate groups)
    load_chunk(0, 0); CP_COMMIT();
    load_chunk(1, 1); CP_COMMIT();

    for (int c = 0; c < NCHUNKS; ++c) {
        const int nt = c >> 3, kt = c & 7;
        const int buf = c % STAGES;

        CP_WAIT1();          // group c complete (c+1 may be pending)
        __syncthreads();     // all warps done with stage (c-1)%3 == (c+2)%3

        if (c + 2 < NCHUNKS) load_chunk(c + 2, (c + 2) % STAGES);
        CP_COMMIT();         // commit (possibly empty) to keep group accounting

        if (kt == 0) {
#pragma unroll
            for (int i = 0; i < 2; ++i)
#pragma unroll
                for (int j = 0; j < 8; ++j)
#pragma unroll
                    for (int q = 0; q < 4; ++q) acc[i][j][q] = 0.0f;
        }

        const uint32_t* As = (const uint32_t*)(smem + buf * STAGE_BYTES);
        const uint32_t* Bs = (const uint32_t*)(smem + buf * STAGE_BYTES + TILE_BYTES);

#pragma unroll
        for (int step = 0; step < 4; ++step) {
            const int k0 = step * 8;
            uint32_t af[2][4], bf[8][2];
#pragma unroll
            for (int i = 0; i < 2; ++i) {
                const int o = a_base + i * 16 * STRIDE + k0;
                af[i][0] = As[o];         af[i][1] = As[o + 8 * STRIDE];
                af[i][2] = As[o + 4];     af[i][3] = As[o + 8 * STRIDE + 4];
            }
#pragma unroll
            for (int j = 0; j < 8; ++j) {
                const int o = b_base + j * 8 * STRIDE + k0;
                bf[j][0] = Bs[o]; bf[j][1] = Bs[o + 4];
            }
#pragma unroll
            for (int i = 0; i < 2; ++i)
#pragma unroll
                for (int j = 0; j < 8; ++j) mma_tf32(acc[i][j], af[i], bf[j]);
        }

        if (kt == 7) {
            // epilogue: dT = fl(fl(t1+ce) - fl(2*dot)); collect near-min set
            const int n0 = nt * BN;
            const float* ceT = ceS + (nt & 1) * BN;
#pragma unroll
            for (int j = 0; j < 8; ++j) {
                const int cl  = warp_n * 64 + j * 8 + 2 * (lane & 3);
                const float ce0 = ceT[cl];
                const float ce1 = ceT[cl + 1];
                const int g0 = n0 + cl;
#pragma unroll
                for (int i = 0; i < 2; ++i)
#pragma unroll
                    for (int h = 0; h < 2; ++h) {
                        const int s = i * 2 + h;
                        const float dv0 = __fsub_rn(__fadd_rn(t1v[s], ce0),
                                                    __fmul_rn(2.0f, acc[i][j][h * 2 + 0]));
                        if (dv0 <= bestd[s] + EPS) {
                            int p = atomicAdd(&g_ccount[rows[s]], 1);
                            if (p < CAP) {
                                g_cand_idx[rows[s] * CAP + p] = g0;
                                g_cand_d[rows[s] * CAP + p] = dv0;
                            }
                            if (dv0 < bestd[s]) bestd[s] = dv0;
                        }
                        const float dv1 = __fsub_rn(__fadd_rn(t1v[s], ce1),
                                                    __fmul_rn(2.0f, acc[i][j][h * 2 + 1]));
                        if (dv1 <= bestd[s] + EPS) {
                            int p = atomicAdd(&g_ccount[rows[s]], 1);
                            if (p < CAP) {
                                g_cand_idx[rows[s] * CAP + p] = g0 + 1;
                                g_cand_d[rows[s] * CAP + p] = dv1;
                            }
                            if (dv1 < bestd[s]) bestd[s] = dv1;
                        }
                    }
            }
        }
    }
}

// ---------------------------------------------------------------------------
// Stage 2: exact fp32 fixup (unchanged — validated).
// ---------------------------------------------------------------------------
__global__ void __launch_bounds__(256)
fixup_kernel(const float* __restrict__ z, const float* __restrict__ cb,
             float* __restrict__ out_idx_f) {
    __shared__ float zrow_s[8][DIM];
    __shared__ int   surv_s[8][SCAP];
    __shared__ int   scount[8];

    const int gw   = (blockIdx.x * blockDim.x + threadIdx.x) >> 5;
    const int lane = threadIdx.x & 31;
    const int w    = threadIdx.x >> 5;
    if (gw >= N_ROWS) return;
    const int row = gw;

    const float* zr = z + (size_t)row * DIM;
    for (int i = lane; i < DIM; i += 32) zrow_s[w][i] = zr[i];
    if (lane == 0) scount[w] = 0;
    __syncwarp();

    const int cnt = g_ccount[row];
    bool fallback = (cnt > CAP);

    if (!fallback) {
        float mn = 3.4e38f;
        for (int e = lane; e < cnt; e += 32)
            mn = fminf(mn, g_cand_d[row * CAP + e]);
#pragma unroll
        for (int off = 16; off > 0; off >>= 1)
            mn = fminf(mn, __shfl_xor_sync(0xffffffffu, mn, off));
        for (int e = lane; e < cnt; e += 32) {
            if (g_cand_d[row * CAP + e] <= mn + EPS) {
                int p = atomicAdd(&scount[w], 1);
                if (p < SCAP) surv_s[w][p] = g_cand_idx[row * CAP + e];
            }
        }
        __syncwarp();
        if (scount[w] > SCAP) fallback = true;
    }

    const float t1 = g_znorm[row];
    float bd = 3.4e38f;
    int   bi = 0x7fffffff;

    if (!fallback) {
        const int ns = scount[w];
        for (int s = lane; s < ns; s += 32) {
            const int k = surv_s[w][s];
            const float* e = cb + (size_t)k * DIM;
            float acc = 0.0f;
#pragma unroll 8
            for (int d = 0; d < DIM; ++d) acc = fmaf(zrow_s[w][d], e[d], acc);
            const float dv = __fsub_rn(__fadd_rn(t1, g_ce[k]),
                                       __fmul_rn(2.0f, acc));
            if (dv < bd || (dv == bd && k < bi)) { bd = dv; bi = k; }
        }
    } else {
        for (int k = lane; k < KCODES; k += 32) {
            const float* e = cb + (size_t)k * DIM;
            float acc = 0.0f;
#pragma unroll 8
            for (int d = 0; d < DIM; ++d) acc = fmaf(zrow_s[w][d], e[d], acc);
            const float dv = __fsub_rn(__fadd_rn(t1, g_ce[k]),
                                       __fmul_rn(2.0f, acc));
            if (dv < bd || (dv == bd && k < bi)) { bd = dv; bi = k; }
        }
    }
#pragma unroll
    for (int off = 16; off > 0; off >>= 1) {
        const float od = __shfl_down_sync(0xffffffffu, bd, off);
        const int   oi = __shfl_down_sync(0xffffffffu, bi, off);
        if (od < bd || (od == bd && oi < bi)) { bd = od; bi = oi; }
    }
    if (lane == 0) {
        g_indices[row] = bi;
        if (out_idx_f) out_idx_f[row] = (float)bi;
    }
}

// ---------------------------------------------------------------------------
// Gather + straight-through output + loss (unchanged — validated)
// ---------------------------------------------------------------------------
__global__ void gather_loss_kernel(const float* __restrict__ z,
                                   const float* __restrict__ cb,
                                   float* __restrict__ out_zq) {
    const int nvec = TOTAL_ELEMS / 4;
    float lsum = 0.0f;
    for (int i4 = blockIdx.x * blockDim.x + threadIdx.x; i4 < nvec;
         i4 += gridDim.x * blockDim.x) {
        const int row  = i4 >> 6;
        const int dc   = (i4 & 63) << 2;
        const int code = g_indices[row];
        const float4 e  = *(const float4*)(cb + (size_t)code * DIM + dc);
        const float4 zz = *(const float4*)(z + (size_t)i4 * 4);
        float4 o;
        float d0 = __fsub_rn(e.x, zz.x); o.x = __fadd_rn(zz.x, d0);
        float d1 = __fsub_rn(e.y, zz.y); o.y = __fadd_rn(zz.y, d1);
        float d2 = __fsub_rn(e.z, zz.z); o.z = __fadd_rn(zz.z, d2);
        float d3 = __fsub_rn(e.w, zz.w); o.w = __fadd_rn(zz.w, d3);
        lsum += d0 * d0 + d1 * d1 + d2 * d2 + d3 * d3;
        *(float4*)(out_zq + (size_t)i4 * 4) = o;
    }
#pragma unroll
    for (int off = 16; off > 0; off >>= 1)
        lsum += __shfl_down_sync(0xffffffffu, lsum, off);
    __shared__ float wsum[8];
    if ((threadIdx.x & 31) == 0) wsum[threadIdx.x >> 5] = lsum;
    __syncthreads();
    if (threadIdx.x < 8) {
        float v = wsum[threadIdx.x];
#pragma unroll
        for (int off = 4; off > 0; off >>= 1)
            v += __shfl_down_sync(0x000000ffu, v, off);
        if (threadIdx.x == 0) atomicAdd(&g_loss, v);
    }
}

__global__ void finalize_kernel(float* __restrict__ out_loss) {
    float m = __fdiv_rn(g_loss, (float)TOTAL_ELEMS);
    out_loss[0] = __fadd_rn(m, __fmul_rn(0.25f, m));
}

// ---------------------------------------------------------------------------
extern "C" void kernel_launch(void* const* d_in, const int* in_sizes, int n_in,
                              void* d_out, int out_size) {
    const float* z  = (const float*)d_in[0];
    const float* cb = (const float*)d_in[1];
    float* out = (float*)d_out;

    float* out_zq   = out;
    float* out_loss = (out_size >= TOTAL_ELEMS + 1) ? (out + TOTAL_ELEMS) : nullptr;
    float* out_idx  = (out_size >= TOTAL_ELEMS + 1 + N_ROWS)
                        ? (out + TOTAL_ELEMS + 1) : nullptr;

    cudaFuncSetAttribute(argmin_mma_kernel,
                         cudaFuncAttributeMaxDynamicSharedMemorySize, SMEM_BYTES);

    float *ztf, *ctf;
    cudaGetSymbolAddress((void**)&ztf, g_ztf);
    cudaGetSymbolAddress((void**)&ctf, g_ctf);

    // 1) row norms + zero loss/counters; tf32 pre-convert
    rownorm_kernel<<<N_ROWS / 8, 256>>>(z, 0, N_ROWS);
    rownorm_kernel<<<KCODES / 8, 256>>>(cb, 1, KCODES);
    cvt_kernel<<<TOTAL_ELEMS / 4 / 256, 256>>>(z, ztf, TOTAL_ELEMS / 4);
    cvt_kernel<<<CB_ELEMS / 4 / 256, 256>>>(cb, ctf, CB_ELEMS / 4);

    // 2) 3-stage pipelined tf32 tensor-core GEMM -> candidate shortlist
    argmin_mma_kernel<<<N_ROWS / BM, 256, SMEM_BYTES>>>(ztf, ctf);

    // 3) exact fp32 fixup -> final indices
    fixup_kernel<<<(N_ROWS * 32) / 256, 256>>>(z, cb, out_idx);

    // 4) outputs
    gather_loss_kernel<<<2048, 256>>>(z, cb, out_zq);
    if (out_loss) finalize_kernel<<<1, 1>>>(out_loss);
}